// round 1
// baseline (speedup 1.0000x reference)
#include <cuda_runtime.h>
#include <math.h>

// ---------------- problem constants ----------------
#define BB   4
#define SS   1024
#define DD   1024
#define HH   16
#define HDIM 64
#define LL   2
#define DFF  4096
#define MM   (BB*SS)        // 4096 rows

// ---------------- static device scratch (no runtime alloc allowed) ----------
__device__ __align__(256) float g_q   [(size_t)MM*DD];
__device__ __align__(256) float g_k   [(size_t)MM*DD];
__device__ __align__(256) float g_v   [(size_t)MM*DD];
__device__ __align__(256) float g_ctx [(size_t)MM*DD];
__device__ __align__(256) float g_tmp [(size_t)MM*DD];
__device__ __align__(256) float g_ffn1[(size_t)MM*DFF];
__device__ __align__(256) float g_attn[(size_t)MM*DD];
__device__ __align__(256) float g_hs  [(size_t)MM*DD];
__device__ __align__(256) float g_scores[(size_t)BB*HH*SS*SS];   // 268 MB

// ---------------- helpers ----------------
__device__ __forceinline__ unsigned long long splat2(float a) {
    unsigned long long r;
    asm("mov.b64 %0, {%1, %1};" : "=l"(r) : "f"(a));
    return r;
}
__device__ __forceinline__ void fma2(unsigned long long &d,
                                     unsigned long long a,
                                     unsigned long long b) {
    asm("fma.rn.f32x2 %0, %1, %2, %0;" : "+l"(d) : "l"(a), "l"(b));
}
__device__ __forceinline__ void unpack2(float &lo, float &hi, unsigned long long p) {
    asm("mov.b64 {%0, %1}, %2;" : "=f"(lo), "=f"(hi) : "l"(p));
}
__device__ __forceinline__ float gelu_exact(float x) {
    return 0.5f * x * (1.0f + erff(x * 0.70710678118654752440f));
}

// ---------------- generic SGEMM: C = A[M,K] * B[K,N] + bias (opt. GELU) -----
// 128x128 block tile, BK=16, 256 threads, 8x8 per thread, packed f32x2 FMA.
template<int ACT>
__global__ __launch_bounds__(256, 2) void sgemm_bias(
    const float* __restrict__ A, const float* __restrict__ Bw,
    const float* __restrict__ bias, float* __restrict__ C,
    int M, int N, int K)
{
    __shared__ float As[16][128];
    __shared__ float Bs[16][128];
    const int tid = threadIdx.x;
    const int bm  = blockIdx.y * 128;
    const int bn  = blockIdx.x * 128;
    const int tx  = tid & 15;
    const int ty  = tid >> 4;

    const int arow = tid >> 2;           // 0..63 (+64 for second pass)
    const int acol = (tid & 3) << 2;     // 0,4,8,12
    const int brow = tid >> 5;           // 0..7 (+8 second)
    const int bcol = (tid & 31) << 2;    // 0..124

    unsigned long long acc[8][4];
    #pragma unroll
    for (int i = 0; i < 8; i++)
        #pragma unroll
        for (int j = 0; j < 4; j++) acc[i][j] = 0ull;

    for (int k0 = 0; k0 < K; k0 += 16) {
        #pragma unroll
        for (int t = 0; t < 2; t++) {
            int r = arow + 64 * t;
            float4 av = *(const float4*)&A[(size_t)(bm + r) * K + k0 + acol];
            As[acol + 0][r] = av.x;
            As[acol + 1][r] = av.y;
            As[acol + 2][r] = av.z;
            As[acol + 3][r] = av.w;
        }
        #pragma unroll
        for (int t = 0; t < 2; t++) {
            int r = brow + 8 * t;
            *(float4*)&Bs[r][bcol] =
                *(const float4*)&Bw[(size_t)(k0 + r) * N + bn + bcol];
        }
        __syncthreads();

        #pragma unroll
        for (int kk = 0; kk < 16; kk++) {
            float4 a0 = *(const float4*)&As[kk][ty * 8];
            float4 a1 = *(const float4*)&As[kk][ty * 8 + 4];
            ulonglong2 b0 = *(const ulonglong2*)&Bs[kk][tx * 8];
            ulonglong2 b1 = *(const ulonglong2*)&Bs[kk][tx * 8 + 4];
            unsigned long long av[8];
            av[0] = splat2(a0.x); av[1] = splat2(a0.y);
            av[2] = splat2(a0.z); av[3] = splat2(a0.w);
            av[4] = splat2(a1.x); av[5] = splat2(a1.y);
            av[6] = splat2(a1.z); av[7] = splat2(a1.w);
            unsigned long long bv[4] = { b0.x, b0.y, b1.x, b1.y };
            #pragma unroll
            for (int i = 0; i < 8; i++)
                #pragma unroll
                for (int j = 0; j < 4; j++)
                    fma2(acc[i][j], av[i], bv[j]);
        }
        __syncthreads();
    }

    // epilogue
    const int c = bn + tx * 8;
    float bsv[8];
    #pragma unroll
    for (int j = 0; j < 8; j++) bsv[j] = bias[c + j];

    #pragma unroll
    for (int i = 0; i < 8; i++) {
        int r = bm + ty * 8 + i;
        float o[8];
        #pragma unroll
        for (int j = 0; j < 4; j++) unpack2(o[2*j], o[2*j+1], acc[i][j]);
        #pragma unroll
        for (int j = 0; j < 8; j++) {
            float v = o[j] + bsv[j];
            if (ACT == 1) v = gelu_exact(v);
            o[j] = v;
        }
        *(float4*)&C[(size_t)r * N + c]     = make_float4(o[0], o[1], o[2], o[3]);
        *(float4*)&C[(size_t)r * N + c + 4] = make_float4(o[4], o[5], o[6], o[7]);
    }
}

// ---------------- attention scores: S = Q K^T * scale + mask ----------------
// grid (S/64, S/64, B*H), block 256; 64x64 tile, K=64 in one shot.
__global__ __launch_bounds__(256) void attn_scores(
    const float* __restrict__ q, const float* __restrict__ kmat,
    const float* __restrict__ mask, float* __restrict__ scores)
{
    __shared__ float Qs[64][65];
    __shared__ float Ks[64][65];
    const int bh = blockIdx.z;
    const int b  = bh >> 4;
    const int h  = bh & 15;
    const int qi = blockIdx.y * 64;
    const int kj = blockIdx.x * 64;
    const int tid = threadIdx.x;

    #pragma unroll
    for (int i = 0; i < 4; i++) {
        int fidx = tid + i * 256;
        int m  = fidx >> 4;
        int dq = (fidx & 15) << 2;
        float4 qv = *(const float4*)&q[((size_t)(b * SS + qi + m)) * DD + h * HDIM + dq];
        Qs[m][dq + 0] = qv.x; Qs[m][dq + 1] = qv.y;
        Qs[m][dq + 2] = qv.z; Qs[m][dq + 3] = qv.w;
        float4 kv = *(const float4*)&kmat[((size_t)(b * SS + kj + m)) * DD + h * HDIM + dq];
        Ks[m][dq + 0] = kv.x; Ks[m][dq + 1] = kv.y;
        Ks[m][dq + 2] = kv.z; Ks[m][dq + 3] = kv.w;
    }
    __syncthreads();

    const int tx = tid & 15, ty = tid >> 4;
    float acc[4][4] = {};
    #pragma unroll 8
    for (int dd = 0; dd < 64; dd++) {
        float a[4], bb[4];
        #pragma unroll
        for (int i = 0; i < 4; i++) a[i]  = Qs[ty * 4 + i][dd];
        #pragma unroll
        for (int j = 0; j < 4; j++) bb[j] = Ks[tx * 4 + j][dd];
        #pragma unroll
        for (int i = 0; i < 4; i++)
            #pragma unroll
            for (int j = 0; j < 4; j++)
                acc[i][j] += a[i] * bb[j];
    }

    const float scale = 0.125f;   // 1/sqrt(64)
    float mk[4];
    #pragma unroll
    for (int j = 0; j < 4; j++) mk[j] = mask[b * SS + kj + tx * 4 + j];

    #pragma unroll
    for (int i = 0; i < 4; i++) {
        int srow = qi + ty * 4 + i;
        float* outp = &g_scores[0];  // silence unused warning path
        (void)outp;
        float4 o;
        o.x = acc[i][0] * scale + mk[0];
        o.y = acc[i][1] * scale + mk[1];
        o.z = acc[i][2] * scale + mk[2];
        o.w = acc[i][3] * scale + mk[3];
        *(float4*)&scores[(size_t)bh * SS * SS + (size_t)srow * SS + kj + tx * 4] = o;
    }
}

// ---------------- softmax over last dim + head_mask scale -------------------
// one warp per row (S=1024 -> 32 elems/lane), 8 warps/block.
__global__ __launch_bounds__(256) void softmax_hm(
    float* __restrict__ scores, const float* __restrict__ head_mask, int layer)
{
    const int row  = blockIdx.x * 8 + (threadIdx.x >> 5);
    const int lane = threadIdx.x & 31;
    const int bh   = row >> 10;           // row / S
    const int h    = bh & (HH - 1);
    const float hm = head_mask[layer * HH + h];

    float4* p = (float4*)(scores + (size_t)row * SS);
    float4 v[8];
    float mx = -INFINITY;
    #pragma unroll
    for (int i = 0; i < 8; i++) {
        v[i] = p[lane + i * 32];
        mx = fmaxf(mx, fmaxf(fmaxf(v[i].x, v[i].y), fmaxf(v[i].z, v[i].w)));
    }
    #pragma unroll
    for (int off = 16; off > 0; off >>= 1)
        mx = fmaxf(mx, __shfl_xor_sync(0xffffffffu, mx, off));

    float sum = 0.f;
    #pragma unroll
    for (int i = 0; i < 8; i++) {
        v[i].x = __expf(v[i].x - mx);
        v[i].y = __expf(v[i].y - mx);
        v[i].z = __expf(v[i].z - mx);
        v[i].w = __expf(v[i].w - mx);
        sum += v[i].x + v[i].y + v[i].z + v[i].w;
    }
    #pragma unroll
    for (int off = 16; off > 0; off >>= 1)
        sum += __shfl_xor_sync(0xffffffffu, sum, off);

    const float inv = hm / sum;
    #pragma unroll
    for (int i = 0; i < 8; i++) {
        v[i].x *= inv; v[i].y *= inv; v[i].z *= inv; v[i].w *= inv;
        p[lane + i * 32] = v[i];
    }
}

// ---------------- ctx = P V (per b,h), writes (B,S,H,HD) layout -------------
// grid (1, S/64, B*H), block 256; 64x64 output tile, K loop over S.
__global__ __launch_bounds__(256) void attn_ctx(
    const float* __restrict__ probs, const float* __restrict__ v,
    float* __restrict__ ctx)
{
    __shared__ float Ps[64][65];
    __shared__ float Vs[64][65];
    const int bh = blockIdx.z;
    const int b  = bh >> 4;
    const int h  = bh & 15;
    const int si = blockIdx.y * 64;
    const int tid = threadIdx.x;
    const int tx = tid & 15, ty = tid >> 4;

    const float* pbase = probs + (size_t)bh * SS * SS;
    float acc[4][4] = {};

    for (int t0 = 0; t0 < SS; t0 += 64) {
        #pragma unroll
        for (int i = 0; i < 4; i++) {
            int fidx = tid + i * 256;
            int m  = fidx >> 4;
            int dq = (fidx & 15) << 2;
            float4 pv = *(const float4*)&pbase[(size_t)(si + m) * SS + t0 + dq];
            Ps[m][dq + 0] = pv.x; Ps[m][dq + 1] = pv.y;
            Ps[m][dq + 2] = pv.z; Ps[m][dq + 3] = pv.w;
            float4 vv = *(const float4*)&v[((size_t)(b * SS + t0 + m)) * DD + h * HDIM + dq];
            Vs[m][dq + 0] = vv.x; Vs[m][dq + 1] = vv.y;
            Vs[m][dq + 2] = vv.z; Vs[m][dq + 3] = vv.w;
        }
        __syncthreads();
        #pragma unroll 8
        for (int tt = 0; tt < 64; tt++) {
            float a[4], bb[4];
            #pragma unroll
            for (int i = 0; i < 4; i++) a[i]  = Ps[ty * 4 + i][tt];
            #pragma unroll
            for (int j = 0; j < 4; j++) bb[j] = Vs[tt][tx * 4 + j];
            #pragma unroll
            for (int i = 0; i < 4; i++)
                #pragma unroll
                for (int j = 0; j < 4; j++)
                    acc[i][j] += a[i] * bb[j];
        }
        __syncthreads();
    }

    #pragma unroll
    for (int i = 0; i < 4; i++) {
        int s = si + ty * 4 + i;
        float4 o = make_float4(acc[i][0], acc[i][1], acc[i][2], acc[i][3]);
        *(float4*)&ctx[((size_t)(b * SS + s)) * DD + h * HDIM + tx * 4] = o;
    }
}

// ---------------- residual + LayerNorm: out = LN(x + y) * g + b -------------
// one block (256 threads) per row of D=1024.
__global__ __launch_bounds__(256) void ln_residual(
    const float* __restrict__ x, const float* __restrict__ y,
    const float* __restrict__ g, const float* __restrict__ b,
    float* __restrict__ out)
{
    const int row = blockIdx.x;
    const int tid = threadIdx.x;
    const float4* xp = (const float4*)(x + (size_t)row * DD);
    const float4* yp = (const float4*)(y + (size_t)row * DD);

    float4 xv = xp[tid];
    float4 yv = yp[tid];
    float4 s4 = make_float4(xv.x + yv.x, xv.y + yv.y, xv.z + yv.z, xv.w + yv.w);

    float s  = s4.x + s4.y + s4.z + s4.w;
    float ss = s4.x * s4.x + s4.y * s4.y + s4.z * s4.z + s4.w * s4.w;

    const int lane = tid & 31, warp = tid >> 5;
    #pragma unroll
    for (int off = 16; off > 0; off >>= 1) {
        s  += __shfl_xor_sync(0xffffffffu, s, off);
        ss += __shfl_xor_sync(0xffffffffu, ss, off);
    }
    __shared__ float ws[8], wss[8];
    if (lane == 0) { ws[warp] = s; wss[warp] = ss; }
    __syncthreads();
    if (warp == 0) {
        float a  = (lane < 8) ? ws[lane]  : 0.f;
        float aa = (lane < 8) ? wss[lane] : 0.f;
        #pragma unroll
        for (int off = 4; off > 0; off >>= 1) {
            a  += __shfl_xor_sync(0xffffffffu, a, off);
            aa += __shfl_xor_sync(0xffffffffu, aa, off);
        }
        if (lane == 0) { ws[0] = a; wss[0] = aa; }
    }
    __syncthreads();
    const float mean = ws[0] * (1.0f / DD);
    const float var  = wss[0] * (1.0f / DD) - mean * mean;
    const float inv  = rsqrtf(var + 1e-12f);

    const float4 gv = ((const float4*)g)[tid];
    const float4 bv = ((const float4*)b)[tid];
    float4 o;
    o.x = (s4.x - mean) * inv * gv.x + bv.x;
    o.y = (s4.y - mean) * inv * gv.y + bv.y;
    o.z = (s4.z - mean) * inv * gv.z + bv.z;
    o.w = (s4.w - mean) * inv * gv.w + bv.w;
    ((float4*)(out + (size_t)row * DD))[tid] = o;
}

// ---------------- host orchestration ----------------
extern "C" void kernel_launch(void* const* d_in, const int* in_sizes, int n_in,
                              void* d_out, int out_size)
{
    const float* hidden = (const float*)d_in[0];
    const float* amask  = (const float*)d_in[1];
    const float* hmask  = (const float*)d_in[2];
    const float* q_w    = (const float*)d_in[3];
    const float* q_b    = (const float*)d_in[4];
    const float* k_w    = (const float*)d_in[5];
    const float* k_b    = (const float*)d_in[6];
    const float* v_w    = (const float*)d_in[7];
    const float* v_b    = (const float*)d_in[8];
    const float* o_w    = (const float*)d_in[9];
    const float* o_b    = (const float*)d_in[10];
    const float* aln_g  = (const float*)d_in[11];
    const float* aln_b  = (const float*)d_in[12];
    const float* w1     = (const float*)d_in[13];
    const float* b1     = (const float*)d_in[14];
    const float* w2     = (const float*)d_in[15];
    const float* b2     = (const float*)d_in[16];
    const float* fln_g  = (const float*)d_in[17];
    const float* fln_b  = (const float*)d_in[18];
    float* out = (float*)d_out;

    float *qb, *kb, *vb, *ctxb, *tmpb, *ffn1b, *attnb, *hsb, *scb;
    cudaGetSymbolAddress((void**)&qb,    g_q);
    cudaGetSymbolAddress((void**)&kb,    g_k);
    cudaGetSymbolAddress((void**)&vb,    g_v);
    cudaGetSymbolAddress((void**)&ctxb,  g_ctx);
    cudaGetSymbolAddress((void**)&tmpb,  g_tmp);
    cudaGetSymbolAddress((void**)&ffn1b, g_ffn1);
    cudaGetSymbolAddress((void**)&attnb, g_attn);
    cudaGetSymbolAddress((void**)&hsb,   g_hs);
    cudaGetSymbolAddress((void**)&scb,   g_scores);

    const dim3 gemm_n1k1(DD / 128, MM / 128);     // N=1024
    const dim3 gemm_n4(DFF / 128, MM / 128);      // N=4096
    const dim3 sc_grid(SS / 64, SS / 64, BB * HH);
    const dim3 ctx_grid(1, SS / 64, BB * HH);

    for (int l = 0; l < LL; l++) {
        const float* hsin  = (l == 0) ? hidden : hsb;
        float*       hsout = (l == LL - 1) ? out : hsb;

        sgemm_bias<0><<<gemm_n1k1, 256>>>(hsin, q_w, q_b, qb, MM, DD, DD);
        sgemm_bias<0><<<gemm_n1k1, 256>>>(hsin, k_w, k_b, kb, MM, DD, DD);
        sgemm_bias<0><<<gemm_n1k1, 256>>>(hsin, v_w, v_b, vb, MM, DD, DD);

        attn_scores<<<sc_grid, 256>>>(qb, kb, amask, scb);
        softmax_hm<<<(BB * HH * SS) / 8, 256>>>(scb, hmask, l);
        attn_ctx<<<ctx_grid, 256>>>(scb, vb, ctxb);

        sgemm_bias<0><<<gemm_n1k1, 256>>>(ctxb, o_w, o_b, tmpb, MM, DD, DD);
        ln_residual<<<MM, 256>>>(hsin, tmpb, aln_g, aln_b, attnb);

        sgemm_bias<1><<<gemm_n4, 256>>>(attnb, w1 + (size_t)l * DD * DFF,
                                        b1 + (size_t)l * DFF, ffn1b, MM, DFF, DD);
        sgemm_bias<0><<<gemm_n1k1, 256>>>(ffn1b, w2 + (size_t)l * DFF * DD,
                                          b2 + (size_t)l * DD, tmpb, MM, DD, DFF);
        ln_residual<<<MM, 256>>>(attnb, tmpb, fln_g + (size_t)l * DD,
                                 fln_b + (size_t)l * DD, hsout);
    }
}

// round 3
// speedup vs baseline: 2.7071x; 2.7071x over previous
#include <cuda_runtime.h>
#include <cuda_bf16.h>
#include <math.h>
#include <stdint.h>

// ---------------- problem constants ----------------
#define BB   4
#define SS   1024
#define DD   1024
#define HH   16
#define HDIM 64
#define LL   2
#define DFF  4096
#define MM   (BB*SS)

// ---------------- static device scratch ----------------
__device__ __align__(256) float g_scores[(size_t)BB*HH*SS*SS];    // 268MB
__device__ __align__(256) float g_tmp [(size_t)MM*DD];
__device__ __align__(256) float g_attn[(size_t)MM*DD];
__device__ __align__(256) float g_hs  [(size_t)MM*DD];

__device__ __align__(256) __nv_bfloat16 g_hs_h [(size_t)MM*DD];
__device__ __align__(256) __nv_bfloat16 g_hs_l [(size_t)MM*DD];
__device__ __align__(256) __nv_bfloat16 g_q_h  [(size_t)MM*DD];
__device__ __align__(256) __nv_bfloat16 g_q_l  [(size_t)MM*DD];
__device__ __align__(256) __nv_bfloat16 g_k_h  [(size_t)MM*DD];
__device__ __align__(256) __nv_bfloat16 g_k_l  [(size_t)MM*DD];
__device__ __align__(256) __nv_bfloat16 g_v_h  [(size_t)MM*DD];
__device__ __align__(256) __nv_bfloat16 g_v_l  [(size_t)MM*DD];
__device__ __align__(256) __nv_bfloat16 g_ctx_h[(size_t)MM*DD];
__device__ __align__(256) __nv_bfloat16 g_ctx_l[(size_t)MM*DD];
__device__ __align__(256) __nv_bfloat16 g_attn_h[(size_t)MM*DD];
__device__ __align__(256) __nv_bfloat16 g_attn_l[(size_t)MM*DD];
__device__ __align__(256) __nv_bfloat16 g_ffn1_h[(size_t)MM*DFF];
__device__ __align__(256) __nv_bfloat16 g_ffn1_l[(size_t)MM*DFF];
__device__ __align__(256) __nv_bfloat16 g_p_h  [(size_t)BB*HH*SS*SS];
__device__ __align__(256) __nv_bfloat16 g_p_l  [(size_t)BB*HH*SS*SS];

__device__ __align__(256) __nv_bfloat16 g_wq_h[(size_t)DD*DD];
__device__ __align__(256) __nv_bfloat16 g_wq_l[(size_t)DD*DD];
__device__ __align__(256) __nv_bfloat16 g_wk_h[(size_t)DD*DD];
__device__ __align__(256) __nv_bfloat16 g_wk_l[(size_t)DD*DD];
__device__ __align__(256) __nv_bfloat16 g_wv_h[(size_t)DD*DD];
__device__ __align__(256) __nv_bfloat16 g_wv_l[(size_t)DD*DD];
__device__ __align__(256) __nv_bfloat16 g_wo_h[(size_t)DD*DD];
__device__ __align__(256) __nv_bfloat16 g_wo_l[(size_t)DD*DD];
__device__ __align__(256) __nv_bfloat16 g_w1_h[(size_t)LL*DD*DFF];
__device__ __align__(256) __nv_bfloat16 g_w1_l[(size_t)LL*DD*DFF];
__device__ __align__(256) __nv_bfloat16 g_w2_h[(size_t)LL*DFF*DD];
__device__ __align__(256) __nv_bfloat16 g_w2_l[(size_t)LL*DFF*DD];

// ---------------- asm helpers ----------------
__device__ __forceinline__ uint32_t smem_u32(const void* p) {
    uint32_t a;
    asm("{ .reg .u64 t; cvta.to.shared.u64 t, %1; cvt.u32.u64 %0, t; }"
        : "=r"(a) : "l"(p));
    return a;
}
#define CP16(dst, src) asm volatile("cp.async.cg.shared.global [%0], [%1], 16;" :: "r"(dst), "l"(src) : "memory")
#define CPCOMMIT()     asm volatile("cp.async.commit_group;" ::: "memory")
#define CPWAIT1()      asm volatile("cp.async.wait_group 1;" ::: "memory")
#define CPWAIT0()      asm volatile("cp.async.wait_group 0;" ::: "memory")

__device__ __forceinline__ void ldsm4(uint32_t* r, uint32_t a) {
    asm volatile("ldmatrix.sync.aligned.m8n8.x4.shared.b16 {%0,%1,%2,%3}, [%4];"
        : "=r"(r[0]), "=r"(r[1]), "=r"(r[2]), "=r"(r[3]) : "r"(a));
}
__device__ __forceinline__ void ldsm4t(uint32_t* r, uint32_t a) {
    asm volatile("ldmatrix.sync.aligned.m8n8.x4.trans.shared.b16 {%0,%1,%2,%3}, [%4];"
        : "=r"(r[0]), "=r"(r[1]), "=r"(r[2]), "=r"(r[3]) : "r"(a));
}
__device__ __forceinline__ void mma_bf16(float* c, const uint32_t* a, const uint32_t* b) {
    asm volatile(
        "mma.sync.aligned.m16n8k16.row.col.f32.bf16.bf16.f32 "
        "{%0,%1,%2,%3}, {%4,%5,%6,%7}, {%8,%9}, {%0,%1,%2,%3};"
        : "+f"(c[0]), "+f"(c[1]), "+f"(c[2]), "+f"(c[3])
        : "r"(a[0]), "r"(a[1]), "r"(a[2]), "r"(a[3]), "r"(b[0]), "r"(b[1]));
}
__device__ __forceinline__ float gelu_exact(float x) {
    return 0.5f * x * (1.0f + erff(x * 0.70710678118654752440f));
}
__device__ __forceinline__ void split2(float v0, float v1,
                                       __nv_bfloat162& h2, __nv_bfloat162& l2) {
    __nv_bfloat16 h0 = __float2bfloat16(v0);
    __nv_bfloat16 h1 = __float2bfloat16(v1);
    __nv_bfloat16 l0 = __float2bfloat16(v0 - __bfloat162float(h0));
    __nv_bfloat16 l1 = __float2bfloat16(v1 - __bfloat162float(h1));
    h2 = __halves2bfloat162(h0, h1);
    l2 = __halves2bfloat162(l0, l1);
}

// ================== split convert: fp32 -> bf16 hi/lo ==================
__global__ __launch_bounds__(256) void split_bf16(
    const float* __restrict__ src, __nv_bfloat16* __restrict__ h,
    __nv_bfloat16* __restrict__ l)
{
    int idx = blockIdx.x * 256 + threadIdx.x;
    float4 v = ((const float4*)src)[idx];
    __nv_bfloat162 h01, l01, h23, l23;
    split2(v.x, v.y, h01, l01);
    split2(v.z, v.w, h23, l23);
    ((__nv_bfloat162*)h)[idx * 2]     = h01;
    ((__nv_bfloat162*)h)[idx * 2 + 1] = h23;
    ((__nv_bfloat162*)l)[idx * 2]     = l01;
    ((__nv_bfloat162*)l)[idx * 2 + 1] = l23;
}

// ================== GEMM: C = A*B + bias, bf16x3 via mma.sync ==================
// A[M,K] bf16 hi/lo row-major, B[K,N] bf16 hi/lo row-major.
// 128x128 tile, 256 threads, warp grid 2(m)x4(n), BK=32, double-buffered cp.async.
// smem stage: A_h[128][40b16] A_l B_h[32][136b16] B_l
#define GM_STAGE 37888
template<int ACT, int WF32, int WSPLIT>
__global__ __launch_bounds__(256) void gemm_bf16x3(
    const __nv_bfloat16* __restrict__ Ah, const __nv_bfloat16* __restrict__ Al,
    const __nv_bfloat16* __restrict__ Bh, const __nv_bfloat16* __restrict__ Bl,
    const float* __restrict__ bias,
    float* __restrict__ Cf, __nv_bfloat16* __restrict__ Ch,
    __nv_bfloat16* __restrict__ Cl, int M, int N, int K)
{
    extern __shared__ char sm[];
    const uint32_t smb = smem_u32(sm);
    const int tid = threadIdx.x, lane = tid & 31, wid = tid >> 5;
    const int warp_m = wid >> 2, warp_n = wid & 3;
    const int bm = blockIdx.y * 128, bn = blockIdx.x * 128;

    float c[4][4][4];
    #pragma unroll
    for (int i = 0; i < 4; i++)
        #pragma unroll
        for (int j = 0; j < 4; j++)
            #pragma unroll
            for (int q = 0; q < 4; q++) c[i][j][q] = 0.f;

    const int rowA  = (lane & 7) + ((lane >> 3) & 1) * 8;
    const int kselA = (lane >> 4) * 8;
    const int kB    = (lane & 7) + ((lane >> 3) & 1) * 8;
    const int nB    = ((lane >> 4) & 1) * 8;

    auto load_stage = [&](int s, int k0) {
        uint32_t base = smb + s * GM_STAGE;
        #pragma unroll
        for (int i = 0; i < 2; i++) {
            int cidx = tid + i * 256;
            int row = cidx >> 2, kc = (cidx & 3) << 3;
            size_t g = (size_t)(bm + row) * K + k0 + kc;
            CP16(base + row * 80 + kc * 2, Ah + g);
            CP16(base + 10240 + row * 80 + kc * 2, Al + g);
        }
        #pragma unroll
        for (int i = 0; i < 2; i++) {
            int cidx = tid + i * 256;
            int k = cidx >> 4, nc = (cidx & 15) << 3;
            size_t g = (size_t)(k0 + k) * N + bn + nc;
            CP16(base + 20480 + k * 272 + nc * 2, Bh + g);
            CP16(base + 29184 + k * 272 + nc * 2, Bl + g);
        }
        CPCOMMIT();
    };

    auto compute = [&](int s) {
        uint32_t bAh = smb + s * GM_STAGE;
        uint32_t bAl = bAh + 10240;
        uint32_t bBh = bAh + 20480;
        uint32_t bBl = bAh + 29184;
        #pragma unroll
        for (int ks = 0; ks < 2; ks++) {
            uint32_t ah[4][4], al[4][4], bh[4][2], bl[4][2];
            #pragma unroll
            for (int mt = 0; mt < 4; mt++) {
                uint32_t off = (uint32_t)((warp_m * 64 + mt * 16 + rowA) * 80 +
                                          (ks * 16 + kselA) * 2);
                ldsm4(ah[mt], bAh + off);
                ldsm4(al[mt], bAl + off);
            }
            #pragma unroll
            for (int ntp = 0; ntp < 2; ntp++) {
                uint32_t off = (uint32_t)((ks * 16 + kB) * 272 +
                                          (warp_n * 32 + ntp * 16 + nB) * 2);
                uint32_t r[4];
                ldsm4t(r, bBh + off);
                bh[2*ntp][0] = r[0]; bh[2*ntp][1] = r[1];
                bh[2*ntp+1][0] = r[2]; bh[2*ntp+1][1] = r[3];
                ldsm4t(r, bBl + off);
                bl[2*ntp][0] = r[0]; bl[2*ntp][1] = r[1];
                bl[2*ntp+1][0] = r[2]; bl[2*ntp+1][1] = r[3];
            }
            #pragma unroll
            for (int mt = 0; mt < 4; mt++)
                #pragma unroll
                for (int nt = 0; nt < 4; nt++) {
                    mma_bf16(c[mt][nt], ah[mt], bh[nt]);
                    mma_bf16(c[mt][nt], ah[mt], bl[nt]);
                    mma_bf16(c[mt][nt], al[mt], bh[nt]);
                }
        }
    };

    const int nt_k = K >> 5;
    load_stage(0, 0);
    for (int t = 0; t < nt_k; t++) {
        if (t + 1 < nt_k) { load_stage((t + 1) & 1, (t + 1) << 5); CPWAIT1(); }
        else              { CPWAIT0(); }
        __syncthreads();
        compute(t & 1);
        __syncthreads();
    }

    // epilogue
    const int g = lane >> 2, tig = lane & 3;
    #pragma unroll
    for (int mt = 0; mt < 4; mt++) {
        #pragma unroll
        for (int nt = 0; nt < 4; nt++) {
            int col = bn + warp_n * 32 + nt * 8 + tig * 2;
            float b0 = bias[col], b1 = bias[col + 1];
            #pragma unroll
            for (int half = 0; half < 2; half++) {
                int row = bm + warp_m * 64 + mt * 16 + g + half * 8;
                float v0 = c[mt][nt][half * 2 + 0] + b0;
                float v1 = c[mt][nt][half * 2 + 1] + b1;
                if (ACT) { v0 = gelu_exact(v0); v1 = gelu_exact(v1); }
                if (WF32)
                    *(float2*)&Cf[(size_t)row * N + col] = make_float2(v0, v1);
                if (WSPLIT) {
                    __nv_bfloat162 h2, l2;
                    split2(v0, v1, h2, l2);
                    *(__nv_bfloat162*)&Ch[(size_t)row * N + col] = h2;
                    *(__nv_bfloat162*)&Cl[(size_t)row * N + col] = l2;
                }
            }
        }
    }
}

// ================== attention scores: S = QK^T*scale + mask ==================
// 128x128 per block, K-dim = 64 (single load). Q,K both [B*S, D] bf16 slices.
// smem: Qh[128][72b16] Ql Kh Kl  (stride 144B)
__global__ __launch_bounds__(256) void attn_scores_mma(
    const __nv_bfloat16* __restrict__ Qh, const __nv_bfloat16* __restrict__ Ql,
    const __nv_bfloat16* __restrict__ Kh, const __nv_bfloat16* __restrict__ Kl,
    const float* __restrict__ mask, float* __restrict__ scores)
{
    extern __shared__ char sm[];
    const uint32_t smb = smem_u32(sm);
    const int tid = threadIdx.x, lane = tid & 31, wid = tid >> 5;
    const int warp_m = wid >> 2, warp_n = wid & 3;
    const int bh = blockIdx.z, b = bh >> 4, h = bh & 15;
    const int si = blockIdx.y * 128, tj = blockIdx.x * 128;

    #pragma unroll
    for (int i = 0; i < 4; i++) {
        int cidx = tid + i * 256;
        int row = cidx >> 3, cc = (cidx & 7) << 3;
        size_t gq = (size_t)(b * SS + si + row) * DD + h * 64 + cc;
        size_t gk = (size_t)(b * SS + tj + row) * DD + h * 64 + cc;
        CP16(smb + 0     + row * 144 + cc * 2, Qh + gq);
        CP16(smb + 18432 + row * 144 + cc * 2, Ql + gq);
        CP16(smb + 36864 + row * 144 + cc * 2, Kh + gk);
        CP16(smb + 55296 + row * 144 + cc * 2, Kl + gk);
    }
    CPCOMMIT(); CPWAIT0();
    __syncthreads();

    float c[4][4][4];
    #pragma unroll
    for (int i = 0; i < 4; i++)
        #pragma unroll
        for (int j = 0; j < 4; j++)
            #pragma unroll
            for (int q = 0; q < 4; q++) c[i][j][q] = 0.f;

    const int rowA  = (lane & 7) + ((lane >> 3) & 1) * 8;
    const int kselA = (lane >> 4) * 8;
    // K operand loaded non-trans (B-frag == A-pattern on K[t][d])
    const int rowK  = (lane & 7) + ((lane >> 4) & 1) * 8;   // t offset within 16
    const int dselK = ((lane >> 3) & 1) * 8;

    #pragma unroll
    for (int ks = 0; ks < 4; ks++) {
        uint32_t ah[4][4], al[4][4], bhreg[4][2], blreg[4][2];
        #pragma unroll
        for (int mt = 0; mt < 4; mt++) {
            uint32_t off = (uint32_t)((warp_m * 64 + mt * 16 + rowA) * 144 +
                                      (ks * 16 + kselA) * 2);
            ldsm4(ah[mt], smb + 0 + off);
            ldsm4(al[mt], smb + 18432 + off);
        }
        #pragma unroll
        for (int ntp = 0; ntp < 2; ntp++) {
            uint32_t off = (uint32_t)((warp_n * 32 + ntp * 16 + rowK) * 144 +
                                      (ks * 16 + dselK) * 2);
            uint32_t r[4];
            ldsm4(r, smb + 36864 + off);
            bhreg[2*ntp][0] = r[0]; bhreg[2*ntp][1] = r[1];
            bhreg[2*ntp+1][0] = r[2]; bhreg[2*ntp+1][1] = r[3];
            ldsm4(r, smb + 55296 + off);
            blreg[2*ntp][0] = r[0]; blreg[2*ntp][1] = r[1];
            blreg[2*ntp+1][0] = r[2]; blreg[2*ntp+1][1] = r[3];
        }
        #pragma unroll
        for (int mt = 0; mt < 4; mt++)
            #pragma unroll
            for (int nt = 0; nt < 4; nt++) {
                mma_bf16(c[mt][nt], ah[mt], bhreg[nt]);
                mma_bf16(c[mt][nt], ah[mt], blreg[nt]);
                mma_bf16(c[mt][nt], al[mt], bhreg[nt]);
            }
    }

    const int g = lane >> 2, tig = lane & 3;
    const float scale = 0.125f;
    #pragma unroll
    for (int mt = 0; mt < 4; mt++) {
        #pragma unroll
        for (int nt = 0; nt < 4; nt++) {
            int col = tj + warp_n * 32 + nt * 8 + tig * 2;
            float m0 = mask[b * SS + col], m1 = mask[b * SS + col + 1];
            #pragma unroll
            for (int half = 0; half < 2; half++) {
                int row = si + warp_m * 64 + mt * 16 + g + half * 8;
                float v0 = c[mt][nt][half * 2 + 0] * scale + m0;
                float v1 = c[mt][nt][half * 2 + 1] * scale + m1;
                *(float2*)&scores[(size_t)bh * SS * SS + (size_t)row * SS + col] =
                    make_float2(v0, v1);
            }
        }
    }
}

// ================== softmax + head_mask -> P bf16 hi/lo ==================
__global__ __launch_bounds__(256) void softmax_hm(
    const float* __restrict__ scores, const float* __restrict__ head_mask,
    int layer, __nv_bfloat16* __restrict__ Ph, __nv_bfloat16* __restrict__ Pl)
{
    const int row  = blockIdx.x * 8 + (threadIdx.x >> 5);
    const int lane = threadIdx.x & 31;
    const int bh   = row >> 10;
    const int h    = bh & (HH - 1);
    const float hm = head_mask[layer * HH + h];

    const float4* p = (const float4*)(scores + (size_t)row * SS);
    float4 v[8];
    float mx = -INFINITY;
    #pragma unroll
    for (int i = 0; i < 8; i++) {
        v[i] = p[lane + i * 32];
        mx = fmaxf(mx, fmaxf(fmaxf(v[i].x, v[i].y), fmaxf(v[i].z, v[i].w)));
    }
    #pragma unroll
    for (int off = 16; off > 0; off >>= 1)
        mx = fmaxf(mx, __shfl_xor_sync(0xffffffffu, mx, off));

    float sum = 0.f;
    #pragma unroll
    for (int i = 0; i < 8; i++) {
        v[i].x = __expf(v[i].x - mx);
        v[i].y = __expf(v[i].y - mx);
        v[i].z = __expf(v[i].z - mx);
        v[i].w = __expf(v[i].w - mx);
        sum += v[i].x + v[i].y + v[i].z + v[i].w;
    }
    #pragma unroll
    for (int off = 16; off > 0; off >>= 1)
        sum += __shfl_xor_sync(0xffffffffu, sum, off);

    const float inv = hm / sum;
    __nv_bfloat162* ph = (__nv_bfloat162*)(Ph + (size_t)row * SS);
    __nv_bfloat162* pl = (__nv_bfloat162*)(Pl + (size_t)row * SS);
    #pragma unroll
    for (int i = 0; i < 8; i++) {
        float v0 = v[i].x * inv, v1 = v[i].y * inv;
        float v2 = v[i].z * inv, v3 = v[i].w * inv;
        __nv_bfloat162 h01, l01, h23, l23;
        split2(v0, v1, h01, l01);
        split2(v2, v3, h23, l23);
        int j = lane + i * 32;
        ph[j * 2] = h01; ph[j * 2 + 1] = h23;
        pl[j * 2] = l01; pl[j * 2 + 1] = l23;
    }
}

// ================== ctx = P V  (128s x 64d per block) ==================
// warp grid 4(m)x2(n); BK=32 over t; double-buffered.
// smem stage: Ph[128][40] Pl  Vh[32][72] Vl
#define CX_STAGE 29696
__global__ __launch_bounds__(256) void attn_ctx_mma(
    const __nv_bfloat16* __restrict__ Ph, const __nv_bfloat16* __restrict__ Pl,
    const __nv_bfloat16* __restrict__ Vh, const __nv_bfloat16* __restrict__ Vl,
    __nv_bfloat16* __restrict__ Ch, __nv_bfloat16* __restrict__ Cl)
{
    extern __shared__ char sm[];
    const uint32_t smb = smem_u32(sm);
    const int tid = threadIdx.x, lane = tid & 31, wid = tid >> 5;
    const int warp_m = wid >> 1, warp_n = wid & 1;
    const int bh = blockIdx.y, b = bh >> 4, h = bh & 15;
    const int si = blockIdx.x * 128;

    float c[2][4][4];
    #pragma unroll
    for (int i = 0; i < 2; i++)
        #pragma unroll
        for (int j = 0; j < 4; j++)
            #pragma unroll
            for (int q = 0; q < 4; q++) c[i][j][q] = 0.f;

    const int rowA  = (lane & 7) + ((lane >> 3) & 1) * 8;
    const int kselA = (lane >> 4) * 8;
    const int kB    = (lane & 7) + ((lane >> 3) & 1) * 8;
    const int nB    = ((lane >> 4) & 1) * 8;

    auto load_stage = [&](int s, int t0) {
        uint32_t base = smb + s * CX_STAGE;
        #pragma unroll
        for (int i = 0; i < 2; i++) {
            int cidx = tid + i * 256;
            int row = cidx >> 2, kc = (cidx & 3) << 3;
            size_t g = (size_t)bh * SS * SS + (size_t)(si + row) * SS + t0 + kc;
            CP16(base + row * 80 + kc * 2, Ph + g);
            CP16(base + 10240 + row * 80 + kc * 2, Pl + g);
        }
        {
            int k = tid >> 3, nc = (tid & 7) << 3;
            size_t g = (size_t)(b * SS + t0 + k) * DD + h * 64 + nc;
            CP16(base + 20480 + k * 144 + nc * 2, Vh + g);
            CP16(base + 25088 + k * 144 + nc * 2, Vl + g);
        }
        CPCOMMIT();
    };

    auto compute = [&](int s) {
        uint32_t bPh = smb + s * CX_STAGE;
        uint32_t bPl = bPh + 10240;
        uint32_t bVh = bPh + 20480;
        uint32_t bVl = bPh + 25088;
        #pragma unroll
        for (int ks = 0; ks < 2; ks++) {
            uint32_t ah[2][4], al[2][4], bhreg[4][2], blreg[4][2];
            #pragma unroll
            for (int mt = 0; mt < 2; mt++) {
                uint32_t off = (uint32_t)((warp_m * 32 + mt * 16 + rowA) * 80 +
                                          (ks * 16 + kselA) * 2);
                ldsm4(ah[mt], bPh + off);
                ldsm4(al[mt], bPl + off);
            }
            #pragma unroll
            for (int ntp = 0; ntp < 2; ntp++) {
                uint32_t off = (uint32_t)((ks * 16 + kB) * 144 +
                                          (warp_n * 32 + ntp * 16 + nB) * 2);
                uint32_t r[4];
                ldsm4t(r, bVh + off);
                bhreg[2*ntp][0] = r[0]; bhreg[2*ntp][1] = r[1];
                bhreg[2*ntp+1][0] = r[2]; bhreg[2*ntp+1][1] = r[3];
                ldsm4t(r, bVl + off);
                blreg[2*ntp][0] = r[0]; blreg[2*ntp][1] = r[1];
                blreg[2*ntp+1][0] = r[2]; blreg[2*ntp+1][1] = r[3];
            }
            #pragma unroll
            for (int mt = 0; mt < 2; mt++)
                #pragma unroll
                for (int nt = 0; nt < 4; nt++) {
                    mma_bf16(c[mt][nt], ah[mt], bhreg[nt]);
                    mma_bf16(c[mt][nt], ah[mt], blreg[nt]);
                    mma_bf16(c[mt][nt], al[mt], bhreg[nt]);
                }
        }
    };

    load_stage(0, 0);
    for (int t = 0; t < SS / 32; t++) {
        if (t + 1 < SS / 32) { load_stage((t + 1) & 1, (t + 1) * 32); CPWAIT1(); }
        else                 { CPWAIT0(); }
        __syncthreads();
        compute(t & 1);
        __syncthreads();
    }

    const int g = lane >> 2, tig = lane & 3;
    #pragma unroll
    for (int mt = 0; mt < 2; mt++) {
        #pragma unroll
        for (int nt = 0; nt < 4; nt++) {
            int col = warp_n * 32 + nt * 8 + tig * 2;
            #pragma unroll
            for (int half = 0; half < 2; half++) {
                int s = si + warp_m * 32 + mt * 16 + g + half * 8;
                float v0 = c[mt][nt][half * 2 + 0];
                float v1 = c[mt][nt][half * 2 + 1];
                __nv_bfloat162 h2, l2;
                split2(v0, v1, h2, l2);
                size_t o = (size_t)(b * SS + s) * DD + h * 64 + col;
                *(__nv_bfloat162*)&Ch[o] = h2;
                *(__nv_bfloat162*)&Cl[o] = l2;
            }
        }
    }
}

// ================== residual + LayerNorm (+ split outputs) ==================
__global__ __launch_bounds__(256) void ln_residual(
    const float* __restrict__ x, const float* __restrict__ y,
    const float* __restrict__ g, const float* __restrict__ b,
    float* __restrict__ out, __nv_bfloat16* __restrict__ oh,
    __nv_bfloat16* __restrict__ ol)
{
    const int row = blockIdx.x;
    const int tid = threadIdx.x;
    const float4* xp = (const float4*)(x + (size_t)row * DD);
    const float4* yp = (const float4*)(y + (size_t)row * DD);

    float4 xv = xp[tid];
    float4 yv = yp[tid];
    float4 s4 = make_float4(xv.x + yv.x, xv.y + yv.y, xv.z + yv.z, xv.w + yv.w);

    float s  = s4.x + s4.y + s4.z + s4.w;
    float ss = s4.x * s4.x + s4.y * s4.y + s4.z * s4.z + s4.w * s4.w;

    const int lane = tid & 31, warp = tid >> 5;
    #pragma unroll
    for (int off = 16; off > 0; off >>= 1) {
        s  += __shfl_xor_sync(0xffffffffu, s, off);
        ss += __shfl_xor_sync(0xffffffffu, ss, off);
    }
    __shared__ float ws[8], wss[8];
    if (lane == 0) { ws[warp] = s; wss[warp] = ss; }
    __syncthreads();
    if (warp == 0) {
        float a  = (lane < 8) ? ws[lane]  : 0.f;
        float aa = (lane < 8) ? wss[lane] : 0.f;
        #pragma unroll
        for (int off = 4; off > 0; off >>= 1) {
            a  += __shfl_xor_sync(0xffffffffu, a, off);
            aa += __shfl_xor_sync(0xffffffffu, aa, off);
        }
        if (lane == 0) { ws[0] = a; wss[0] = aa; }
    }
    __syncthreads();
    const float mean = ws[0] * (1.0f / DD);
    const float var  = wss[0] * (1.0f / DD) - mean * mean;
    const float inv  = rsqrtf(var + 1e-12f);

    const float4 gv = ((const float4*)g)[tid];
    const float4 bv = ((const float4*)b)[tid];
    float4 o;
    o.x = (s4.x - mean) * inv * gv.x + bv.x;
    o.y = (s4.y - mean) * inv * gv.y + bv.y;
    o.z = (s4.z - mean) * inv * gv.z + bv.z;
    o.w = (s4.w - mean) * inv * gv.w + bv.w;
    ((float4*)(out + (size_t)row * DD))[tid] = o;

    __nv_bfloat162 h01, l01, h23, l23;
    split2(o.x, o.y, h01, l01);
    split2(o.z, o.w, h23, l23);
    __nv_bfloat162* hp = (__nv_bfloat162*)(oh + (size_t)row * DD);
    __nv_bfloat162* lp = (__nv_bfloat162*)(ol + (size_t)row * DD);
    hp[tid * 2] = h01; hp[tid * 2 + 1] = h23;
    lp[tid * 2] = l01; lp[tid * 2 + 1] = l23;
}

// ================== host orchestration ==================
extern "C" void kernel_launch(void* const* d_in, const int* in_sizes, int n_in,
                              void* d_out, int out_size)
{
    const float* hidden = (const float*)d_in[0];
    const float* amask  = (const float*)d_in[1];
    const float* hmask  = (const float*)d_in[2];
    const float* q_w    = (const float*)d_in[3];
    const float* q_b    = (const float*)d_in[4];
    const float* k_w    = (const float*)d_in[5];
    const float* k_b    = (const float*)d_in[6];
    const float* v_w    = (const float*)d_in[7];
    const float* v_b    = (const float*)d_in[8];
    const float* o_w    = (const float*)d_in[9];
    const float* o_b    = (const float*)d_in[10];
    const float* aln_g  = (const float*)d_in[11];
    const float* aln_b  = (const float*)d_in[12];
    const float* w1     = (const float*)d_in[13];
    const float* b1     = (const float*)d_in[14];
    const float* w2     = (const float*)d_in[15];
    const float* b2     = (const float*)d_in[16];
    const float* fln_g  = (const float*)d_in[17];
    const float* fln_b  = (const float*)d_in[18];
    float* out = (float*)d_out;

    // resolve scratch
    float *scoresb, *tmpb, *attnb, *hsb;
    __nv_bfloat16 *hs_h, *hs_l, *q_h, *q_l, *k_h, *k_l, *v_h, *v_l;
    __nv_bfloat16 *ctx_h, *ctx_l, *attn_h, *attn_l, *ffn1_h, *ffn1_l, *p_h, *p_l;
    __nv_bfloat16 *wq_h, *wq_l, *wk_h, *wk_l, *wv_h, *wv_l, *wo_h, *wo_l;
    __nv_bfloat16 *w1_h, *w1_l, *w2_h, *w2_l;
    cudaGetSymbolAddress((void**)&scoresb, g_scores);
    cudaGetSymbolAddress((void**)&tmpb,  g_tmp);
    cudaGetSymbolAddress((void**)&attnb, g_attn);
    cudaGetSymbolAddress((void**)&hsb,   g_hs);
    cudaGetSymbolAddress((void**)&hs_h, g_hs_h);  cudaGetSymbolAddress((void**)&hs_l, g_hs_l);
    cudaGetSymbolAddress((void**)&q_h, g_q_h);    cudaGetSymbolAddress((void**)&q_l, g_q_l);
    cudaGetSymbolAddress((void**)&k_h, g_k_h);    cudaGetSymbolAddress((void**)&k_l, g_k_l);
    cudaGetSymbolAddress((void**)&v_h, g_v_h);    cudaGetSymbolAddress((void**)&v_l, g_v_l);
    cudaGetSymbolAddress((void**)&ctx_h, g_ctx_h);   cudaGetSymbolAddress((void**)&ctx_l, g_ctx_l);
    cudaGetSymbolAddress((void**)&attn_h, g_attn_h); cudaGetSymbolAddress((void**)&attn_l, g_attn_l);
    cudaGetSymbolAddress((void**)&ffn1_h, g_ffn1_h); cudaGetSymbolAddress((void**)&ffn1_l, g_ffn1_l);
    cudaGetSymbolAddress((void**)&p_h, g_p_h);    cudaGetSymbolAddress((void**)&p_l, g_p_l);
    cudaGetSymbolAddress((void**)&wq_h, g_wq_h);  cudaGetSymbolAddress((void**)&wq_l, g_wq_l);
    cudaGetSymbolAddress((void**)&wk_h, g_wk_h);  cudaGetSymbolAddress((void**)&wk_l, g_wk_l);
    cudaGetSymbolAddress((void**)&wv_h, g_wv_h);  cudaGetSymbolAddress((void**)&wv_l, g_wv_l);
    cudaGetSymbolAddress((void**)&wo_h, g_wo_h);  cudaGetSymbolAddress((void**)&wo_l, g_wo_l);
    cudaGetSymbolAddress((void**)&w1_h, g_w1_h);  cudaGetSymbolAddress((void**)&w1_l, g_w1_l);
    cudaGetSymbolAddress((void**)&w2_h, g_w2_h);  cudaGetSymbolAddress((void**)&w2_l, g_w2_l);

    cudaFuncSetAttribute(gemm_bf16x3<0,0,1>, cudaFuncAttributeMaxDynamicSharedMemorySize, 2*GM_STAGE);
    cudaFuncSetAttribute(gemm_bf16x3<0,1,0>, cudaFuncAttributeMaxDynamicSharedMemorySize, 2*GM_STAGE);
    cudaFuncSetAttribute(gemm_bf16x3<1,0,1>, cudaFuncAttributeMaxDynamicSharedMemorySize, 2*GM_STAGE);
    cudaFuncSetAttribute(attn_scores_mma, cudaFuncAttributeMaxDynamicSharedMemorySize, 73728);
    cudaFuncSetAttribute(attn_ctx_mma, cudaFuncAttributeMaxDynamicSharedMemorySize, 2*CX_STAGE);

    // weight / input conversion
    split_bf16<<<(DD*DD)/1024, 256>>>(q_w, wq_h, wq_l);
    split_bf16<<<(DD*DD)/1024, 256>>>(k_w, wk_h, wk_l);
    split_bf16<<<(DD*DD)/1024, 256>>>(v_w, wv_h, wv_l);
    split_bf16<<<(DD*DD)/1024, 256>>>(o_w, wo_h, wo_l);
    split_bf16<<<(LL*DD*DFF)/1024, 256>>>(w1, w1_h, w1_l);
    split_bf16<<<(LL*DFF*DD)/1024, 256>>>(w2, w2_h, w2_l);
    split_bf16<<<(MM*DD)/1024, 256>>>(hidden, hs_h, hs_l);

    const dim3 g1(DD/128, MM/128);
    const dim3 g4(DFF/128, MM/128);
    const dim3 sc_grid(SS/128, SS/128, BB*HH);
    const dim3 cx_grid(SS/128, BB*HH);

    for (int l = 0; l < LL; l++) {
        const float* hsin_f = (l == 0) ? hidden : hsb;
        float* hsout = (l == LL - 1) ? out : hsb;

        gemm_bf16x3<0,0,1><<<g1, 256, 2*GM_STAGE>>>(hs_h, hs_l, wq_h, wq_l, q_b,
            nullptr, q_h, q_l, MM, DD, DD);
        gemm_bf16x3<0,0,1><<<g1, 256, 2*GM_STAGE>>>(hs_h, hs_l, wk_h, wk_l, k_b,
            nullptr, k_h, k_l, MM, DD, DD);
        gemm_bf16x3<0,0,1><<<g1, 256, 2*GM_STAGE>>>(hs_h, hs_l, wv_h, wv_l, v_b,
            nullptr, v_h, v_l, MM, DD, DD);

        attn_scores_mma<<<sc_grid, 256, 73728>>>(q_h, q_l, k_h, k_l, amask, scoresb);
        softmax_hm<<<(BB*HH*SS)/8, 256>>>(scoresb, hmask, l, p_h, p_l);
        attn_ctx_mma<<<cx_grid, 256, 2*CX_STAGE>>>(p_h, p_l, v_h, v_l, ctx_h, ctx_l);

        gemm_bf16x3<0,1,0><<<g1, 256, 2*GM_STAGE>>>(ctx_h, ctx_l, wo_h, wo_l, o_b,
            tmpb, nullptr, nullptr, MM, DD, DD);
        ln_residual<<<MM, 256>>>(hsin_f, tmpb, aln_g, aln_b, attnb, attn_h, attn_l);

        gemm_bf16x3<1,0,1><<<g4, 256, 2*GM_STAGE>>>(attn_h, attn_l,
            w1_h + (size_t)l*DD*DFF, w1_l + (size_t)l*DD*DFF, b1 + (size_t)l*DFF,
            nullptr, ffn1_h, ffn1_l, MM, DFF, DD);
        gemm_bf16x3<0,1,0><<<g1, 256, 2*GM_STAGE>>>(ffn1_h, ffn1_l,
            w2_h + (size_t)l*DFF*DD, w2_l + (size_t)l*DFF*DD, b2 + (size_t)l*DD,
            tmpb, nullptr, nullptr, MM, DD, DFF);
        ln_residual<<<MM, 256>>>(attnb, tmpb, fln_g + (size_t)l*DD,
                                 fln_b + (size_t)l*DD, hsout, hs_h, hs_l);
    }
}